// round 1
// baseline (speedup 1.0000x reference)
#include <cuda_runtime.h>
#include <cuda_bf16.h>
#include <math.h>

// Problem constants
#define BB   64
#define FF   32
#define NN   36
#define REGION 1024
#define HIDDEN 1024
#define ATT    1024
#define FEAT2  3072
#define M1   (BB*FF*NN)       // 73728 rows of spatial GEMM
#define M2   (BB*FF)          // 2048 rows of temporal GEMM

// ---------------- scratch (device globals; no allocation allowed) ----------------
__device__ float g_hproj_s[BB * ATT];        // h @ s_wh_w^T + s_wh_b + s_wv_b
__device__ float g_hproj_t[BB * HIDDEN];     // h @ t_wh_w^T + t_wh_b + t_wv_b
__device__ float g_score1[M1];               // spatial scores [B,F,N]
__device__ float g_feat[M2 * FEAT2];         // concat(obj_att, frame_feats)
__device__ float g_score2[M2];               // temporal scores [B,F]

// ---------------- tiny zero kernel (atomics accumulate into these) ----------------
__global__ void zero_kernel(float* __restrict__ p, int n) {
    int i = blockIdx.x * blockDim.x + threadIdx.x;
    if (i < n) p[i] = 0.0f;
}

// ---------------- hidden-state projection: out[b,a] = h[b]·W[a] + bh[a] + bv[a] ----
__global__ __launch_bounds__(256) void hproj_kernel(
    const float* __restrict__ hidden, const float* __restrict__ Wh,
    const float* __restrict__ bh, const float* __restrict__ bv,
    float* __restrict__ out)
{
    int b = blockIdx.x;
    int achunk = blockIdx.y;  // 0..7, 128 outputs each
    __shared__ float h[HIDDEN];
    for (int i = threadIdx.x; i < HIDDEN; i += 256)
        h[i] = hidden[b * HIDDEN + i];
    __syncthreads();
    int warp = threadIdx.x >> 5, lane = threadIdx.x & 31;
    for (int al = warp; al < 128; al += 8) {
        int a = achunk * 128 + al;
        const float* w = Wh + (size_t)a * HIDDEN;
        float acc = 0.f;
        #pragma unroll 8
        for (int k = lane; k < HIDDEN; k += 32) acc += w[k] * h[k];
        #pragma unroll
        for (int off = 16; off > 0; off >>= 1)
            acc += __shfl_xor_sync(0xffffffffu, acc, off);
        if (lane == 0) out[b * 1024 + a] = acc + bh[a] + bv[a];
    }
}

// ---------------- fused GEMM + tanh-dot epilogue ----------------
// C[m,a] = sum_k A[m,k] * W[a,k]          (A: [M,K] row-major, W: [1024,K] row-major)
// score[m] += sum_a tanh(C[m,a] + hproj[batch(m), a]) * wa[a]
// 128x128x16 tile, 256 threads, 8x8 microtile per thread.
__global__ __launch_bounds__(256) void fused_gemm_score(
    const float* __restrict__ A, const float* __restrict__ W,
    const float* __restrict__ hproj, const float* __restrict__ wa,
    float* __restrict__ score, int M, int K, int rows_per_batch)
{
    __shared__ float As[16][128];
    __shared__ float Bs[16][128];

    const int t  = threadIdx.x;
    const int m0 = blockIdx.x * 128;
    const int n0 = blockIdx.y * 128;
    const int lr = t >> 2;            // 0..63
    const int lq = (t & 3) * 4;       // 0,4,8,12
    const int ty = t >> 4;            // 0..15
    const int tx = t & 15;            // 0..15

    const float* Aptr = A + (size_t)(m0 + lr) * K + lq;
    const float* Bptr = W + (size_t)(n0 + lr) * K + lq;
    const size_t rowK64 = (size_t)64 * K;

    float acc[8][8];
    #pragma unroll
    for (int i = 0; i < 8; i++)
        #pragma unroll
        for (int j = 0; j < 8; j++) acc[i][j] = 0.f;

    for (int k0 = 0; k0 < K; k0 += 16) {
        float4 a0 = *(const float4*)(Aptr + k0);
        float4 a1 = *(const float4*)(Aptr + rowK64 + k0);
        float4 b0 = *(const float4*)(Bptr + k0);
        float4 b1 = *(const float4*)(Bptr + rowK64 + k0);

        As[lq+0][lr] = a0.x; As[lq+1][lr] = a0.y; As[lq+2][lr] = a0.z; As[lq+3][lr] = a0.w;
        As[lq+0][lr+64] = a1.x; As[lq+1][lr+64] = a1.y; As[lq+2][lr+64] = a1.z; As[lq+3][lr+64] = a1.w;
        Bs[lq+0][lr] = b0.x; Bs[lq+1][lr] = b0.y; Bs[lq+2][lr] = b0.z; Bs[lq+3][lr] = b0.w;
        Bs[lq+0][lr+64] = b1.x; Bs[lq+1][lr+64] = b1.y; Bs[lq+2][lr+64] = b1.z; Bs[lq+3][lr+64] = b1.w;
        __syncthreads();

        #pragma unroll
        for (int kk = 0; kk < 16; kk++) {
            float ar[8], br[8];
            *(float4*)(ar)     = *(const float4*)&As[kk][ty * 8];
            *(float4*)(ar + 4) = *(const float4*)&As[kk][ty * 8 + 4];
            *(float4*)(br)     = *(const float4*)&Bs[kk][tx * 8];
            *(float4*)(br + 4) = *(const float4*)&Bs[kk][tx * 8 + 4];
            #pragma unroll
            for (int i = 0; i < 8; i++)
                #pragma unroll
                for (int j = 0; j < 8; j++)
                    acc[i][j] += ar[i] * br[j];
        }
        __syncthreads();
    }

    // Epilogue: tanh + weighted reduction over the 128 columns of this tile
    float part[8];
    #pragma unroll
    for (int i = 0; i < 8; i++) {
        int m = m0 + ty * 8 + i;
        int b = m / rows_per_batch;
        const float* hp = hproj + (size_t)b * 1024 + n0;
        float p = 0.f;
        #pragma unroll
        for (int j = 0; j < 8; j++) {
            int a = tx * 8 + j;
            p += tanhf(acc[i][j] + hp[a]) * wa[n0 + a];
        }
        part[i] = p;
    }
    // reduce across the 16 tx lanes (lanes ty*16 .. ty*16+15 stay in-warp)
    #pragma unroll
    for (int off = 1; off < 16; off <<= 1)
        #pragma unroll
        for (int i = 0; i < 8; i++)
            part[i] += __shfl_xor_sync(0xffffffffu, part[i], off);
    if (tx == 0) {
        #pragma unroll
        for (int i = 0; i < 8; i++)
            atomicAdd(&score[m0 + ty * 8 + i], part[i]);
    }
}

// ---------------- spatial softmax over N=36 + weighted sum + concat ----------------
__global__ __launch_bounds__(256) void spatial_kernel(
    const float* __restrict__ obj, const float* __restrict__ frame,
    const float* __restrict__ score, float* __restrict__ feat)
{
    int bf = blockIdx.x;  // 0..2047
    __shared__ float alpha[NN];
    if (threadIdx.x == 0) {
        float s[NN];
        float mx = -1e30f;
        #pragma unroll
        for (int n = 0; n < NN; n++) { s[n] = score[bf * NN + n]; mx = fmaxf(mx, s[n]); }
        float sum = 0.f;
        #pragma unroll
        for (int n = 0; n < NN; n++) { float e = expf(s[n] - mx); alpha[n] = e; sum += e; }
        float inv = 1.f / sum;
        #pragma unroll
        for (int n = 0; n < NN; n++) alpha[n] *= inv;
    }
    __syncthreads();

    const float* base = obj + (size_t)bf * NN * REGION;
    float* frow = feat + (size_t)bf * FEAT2;
    for (int d = threadIdx.x; d < REGION; d += 256) {
        float acc = 0.f;
        #pragma unroll 6
        for (int n = 0; n < NN; n++) acc += alpha[n] * base[(size_t)n * REGION + d];
        frow[d] = acc;
    }
    const float* frm = frame + (size_t)bf * (2 * HIDDEN);
    for (int d = threadIdx.x; d < 2 * HIDDEN; d += 256)
        frow[REGION + d] = frm[d];
}

// ---------------- temporal softmax over F=32 + weighted sum -> output ----------------
__global__ __launch_bounds__(256) void temporal_kernel(
    const float* __restrict__ feat, const float* __restrict__ score2,
    float* __restrict__ out)
{
    int b = blockIdx.x;  // 0..63
    __shared__ float beta[FF];
    if (threadIdx.x == 0) {
        float s[FF];
        float mx = -1e30f;
        #pragma unroll
        for (int f = 0; f < FF; f++) { s[f] = score2[b * FF + f]; mx = fmaxf(mx, s[f]); }
        float sum = 0.f;
        #pragma unroll
        for (int f = 0; f < FF; f++) { float e = expf(s[f] - mx); beta[f] = e; sum += e; }
        float inv = 1.f / sum;
        #pragma unroll
        for (int f = 0; f < FF; f++) beta[f] *= inv;
    }
    __syncthreads();

    int d0 = blockIdx.y * (FEAT2 / 4);  // 768 columns per y-block
    for (int d = d0 + threadIdx.x; d < d0 + FEAT2 / 4; d += 256) {
        float acc = 0.f;
        #pragma unroll 8
        for (int f = 0; f < FF; f++)
            acc += beta[f] * feat[((size_t)b * FF + f) * FEAT2 + d];
        out[(size_t)b * FEAT2 + d] = acc;
    }
}

// ---------------- launch ----------------
extern "C" void kernel_launch(void* const* d_in, const int* in_sizes, int n_in,
                              void* d_out, int out_size)
{
    const float* frame  = (const float*)d_in[0];
    const float* obj    = (const float*)d_in[1];
    const float* hidden = (const float*)d_in[2];
    const float* s_wh_w = (const float*)d_in[3];
    const float* s_wh_b = (const float*)d_in[4];
    const float* s_wv_w = (const float*)d_in[5];
    const float* s_wv_b = (const float*)d_in[6];
    const float* s_wa_w = (const float*)d_in[7];
    const float* t_wh_w = (const float*)d_in[8];
    const float* t_wh_b = (const float*)d_in[9];
    const float* t_wv_w = (const float*)d_in[10];
    const float* t_wv_b = (const float*)d_in[11];
    const float* t_wa_w = (const float*)d_in[12];
    float* out = (float*)d_out;

    float *p_hs, *p_ht, *p_s1, *p_feat, *p_s2;
    cudaGetSymbolAddress((void**)&p_hs, g_hproj_s);
    cudaGetSymbolAddress((void**)&p_ht, g_hproj_t);
    cudaGetSymbolAddress((void**)&p_s1, g_score1);
    cudaGetSymbolAddress((void**)&p_feat, g_feat);
    cudaGetSymbolAddress((void**)&p_s2, g_score2);

    // hidden-state projections (fold in both biases)
    dim3 hg(BB, 8);
    hproj_kernel<<<hg, 256>>>(hidden, s_wh_w, s_wh_b, s_wv_b, p_hs);
    hproj_kernel<<<hg, 256>>>(hidden, t_wh_w, t_wh_b, t_wv_b, p_ht);

    // spatial attention scores: the 154.6 GFLOP GEMM, fused epilogue
    zero_kernel<<<(M1 + 255) / 256, 256>>>(p_s1, M1);
    dim3 g1(M1 / 128, ATT / 128);
    fused_gemm_score<<<g1, 256>>>(obj, s_wv_w, p_hs, s_wa_w, p_s1,
                                  M1, REGION, FF * NN);

    // softmax over boxes + weighted object sum + concat frame feats
    spatial_kernel<<<M2, 256>>>(obj, frame, p_s1, p_feat);

    // temporal attention scores
    zero_kernel<<<(M2 + 255) / 256, 256>>>(p_s2, M2);
    dim3 g2(M2 / 128, HIDDEN / 128);
    fused_gemm_score<<<g2, 256>>>(p_feat, t_wv_w, p_ht, t_wa_w, p_s2,
                                  M2, FEAT2, FF);

    // softmax over frames + weighted feat sum -> [64, 3072]
    temporal_kernel<<<dim3(BB, 4), 256>>>(p_feat, p_s2, out);
}

// round 3
// speedup vs baseline: 3.5243x; 3.5243x over previous
#include <cuda_runtime.h>
#include <cuda_bf16.h>
#include <math.h>
#include <stdint.h>

// Problem constants
#define BB   64
#define FF   32
#define NN   36
#define REGION 1024
#define HIDDEN 1024
#define FEAT2  3072
#define M1   (BB*FF*NN)       // 73728 rows of spatial GEMM
#define M2   (BB*FF)          // 2048 rows of temporal GEMM

// ---------------- scratch (device globals; no allocation allowed) ----------------
__device__ float g_hproj_s[BB * 1024];
__device__ float g_hproj_t[BB * 1024];
__device__ float g_score1[M1];
__device__ float g_feat[M2 * FEAT2];
__device__ float g_score2[M2];

// ================= PTX helpers =================
__device__ __forceinline__ uint32_t smem_u32(const void* p) {
    uint32_t a;
    asm("{ .reg .u64 t; cvta.to.shared.u64 t, %1; cvt.u32.u64 %0, t; }" : "=r"(a) : "l"(p));
    return a;
}

__device__ __forceinline__ void cp_async16(uint32_t dst, const void* src) {
    asm volatile("cp.async.cg.shared.global [%0], [%1], 16;" :: "r"(dst), "l"(src));
}
#define CP_COMMIT() asm volatile("cp.async.commit_group;" ::: "memory")

__device__ __forceinline__ void ldsm_x4(uint32_t r[4], uint32_t addr) {
    asm volatile("ldmatrix.sync.aligned.m8n8.x4.shared.b16 {%0,%1,%2,%3}, [%4];"
                 : "=r"(r[0]), "=r"(r[1]), "=r"(r[2]), "=r"(r[3]) : "r"(addr));
}

__device__ __forceinline__ void mma_tf32(float c[4], const uint32_t a[4], uint32_t b0, uint32_t b1) {
    asm volatile(
        "mma.sync.aligned.m16n8k8.row.col.f32.tf32.tf32.f32 "
        "{%0,%1,%2,%3}, {%4,%5,%6,%7}, {%8,%9}, {%0,%1,%2,%3};"
        : "+f"(c[0]), "+f"(c[1]), "+f"(c[2]), "+f"(c[3])
        : "r"(a[0]), "r"(a[1]), "r"(a[2]), "r"(a[3]), "r"(b0), "r"(b1));
}

// swizzled offset within a [rows x 32 float] tile (128B rows, SW128 pattern)
__device__ __forceinline__ uint32_t tile_off(int row, int chunk16) {
    return (uint32_t)(row * 128 + ((chunk16 ^ (row & 7)) << 4));
}

// ================= tf32 mma.sync fused GEMM + tanh-dot epilogue =================
// C[m,a] = sum_k A[m,k]*W[a,k]; score[m] += sum_a tanh(C[m,a]+hproj[b(m),a])*wa[a]
// CTA: 128 x NT, 256 threads = 8 warps (2 M x 4 N). Warp tile 64 x (NT/4).
// K-chunks of 32 floats, 3-stage cp.async double... triple buffer.

template <int NT>
__device__ __forceinline__ void load_stage(uint32_t base, const float* Ag, const float* Wg,
                                           int K, int tid) {
    const int TOT = 1024 + NT * 8;          // 16B chunks: A=128rows*8, B=NT*8
    #pragma unroll
    for (int it = 0; it < (1024 + NT * 8) / 256; it++) {
        int id = tid + it * 256;
        uint32_t dst; const float* src;
        if (id < 1024) {
            int r = id >> 3, c = id & 7;
            dst = base + tile_off(r, c);
            src = Ag + (size_t)r * K + c * 4;
        } else {
            int j = id - 1024;
            int r = j >> 3, c = j & 7;
            dst = base + 16384 + tile_off(r, c);
            src = Wg + (size_t)r * K + c * 4;
        }
        cp_async16(dst, src);
    }
    (void)TOT;
}

template <int NT>
__global__ __launch_bounds__(256, 1) void gemm_score_mma(
    const float* __restrict__ A, const float* __restrict__ W,
    const float* __restrict__ hproj, const float* __restrict__ wa,
    float* __restrict__ score, int K, int rpb)
{
    constexpr int WN = NT / 4;          // warp n-extent (64 or 32)
    constexpr int MI = 4;               // 4 m-tiles of 16 -> 64 rows per warp
    constexpr int NI = WN / 8;          // n-tiles of 8 per warp
    constexpr int STAGE = 16384 + NT * 128;
    constexpr int OFF_WA = 3 * STAGE;
    constexpr int OFF_HP = OFF_WA + NT * 4;

    extern __shared__ char smem[];
    const uint32_t sb = smem_u32(smem);
    const int tid = threadIdx.x;
    const int lane = tid & 31;
    const int warp = tid >> 5;
    const int warp_m = warp >> 2;       // 0..1
    const int warp_n = warp & 3;        // 0..3
    const int m0 = blockIdx.x * 128;
    const int n0 = blockIdx.y * NT;
    const int S = K >> 5;

    // epilogue constants into smem
    {
        float* wa_s = (float*)(smem + OFF_WA);
        float* hp_s = (float*)(smem + OFF_HP);
        for (int i = tid; i < NT; i += 256) wa_s[i] = wa[n0 + i];
        int nb = 128 / rpb; if (nb < 1) nb = 1;
        int b0 = m0 / rpb;
        for (int i = tid; i < nb * NT; i += 256)
            hp_s[i] = hproj[(size_t)(b0 + i / NT) * 1024 + n0 + (i % NT)];
    }

    const float* Abase = A + (size_t)m0 * K;
    const float* Wbase = W + (size_t)n0 * K;

    float acc[MI][NI][4];
    #pragma unroll
    for (int i = 0; i < MI; i++)
        #pragma unroll
        for (int j = 0; j < NI; j++)
            #pragma unroll
            for (int q = 0; q < 4; q++) acc[i][j][q] = 0.f;

    // per-thread ldmatrix row/chunk components
    const int lrow = lane & 15;          // row within 16-row group
    const int lhi  = lane >> 4;          // 16B chunk select within k8

    load_stage<NT>(sb, Abase, Wbase, K, tid);       CP_COMMIT();
    load_stage<NT>(sb + STAGE, Abase + 32, Wbase + 32, K, tid); CP_COMMIT();

    int buf = 0;
    for (int kc = 0; kc < S; kc++) {
        if (kc + 2 < S) {
            int nb3 = kc + 2; int bsel = nb3 % 3;
            load_stage<NT>(sb + bsel * STAGE, Abase + nb3 * 32, Wbase + nb3 * 32, K, tid);
        }
        CP_COMMIT();
        asm volatile("cp.async.wait_group 2;" ::: "memory");
        __syncthreads();

        uint32_t a_base = sb + buf * STAGE;
        uint32_t b_base = a_base + 16384;

        #pragma unroll
        for (int s = 0; s < 4; s++) {
            int chunk = s * 2 + lhi;
            uint32_t af[MI][4];
            #pragma unroll
            for (int mi = 0; mi < MI; mi++)
                ldsm_x4(af[mi], a_base + tile_off(warp_m * 64 + mi * 16 + lrow, chunk));
            uint32_t bf[NI][2];
            #pragma unroll
            for (int p = 0; p < NI / 2; p++) {
                uint32_t r[4];
                ldsm_x4(r, b_base + tile_off(warp_n * WN + p * 16 + lrow, chunk));
                bf[2*p][0] = r[0]; bf[2*p][1] = r[2];
                bf[2*p+1][0] = r[1]; bf[2*p+1][1] = r[3];
            }
            #pragma unroll
            for (int mi = 0; mi < MI; mi++)
                #pragma unroll
                for (int ni = 0; ni < NI; ni++)
                    mma_tf32(acc[mi][ni], af[mi], bf[ni][0], bf[ni][1]);
        }
        __syncthreads();
        buf++; if (buf == 3) buf = 0;
    }

    // ---- epilogue: tanh + weighted column reduction ----
    const float* wa_s = (const float*)(smem + OFF_WA);
    const float* hp_s = (const float*)(smem + OFF_HP);
    const int g = lane >> 2, tig = lane & 3;

    #pragma unroll
    for (int mi = 0; mi < MI; mi++) {
        int r0 = warp_m * 64 + mi * 16 + g;
        int r1 = r0 + 8;
        int bl0 = r0 / rpb, bl1 = r1 / rpb;
        const float* hp0 = hp_s + bl0 * NT;
        const float* hp1 = hp_s + bl1 * NT;
        float s0 = 0.f, s1 = 0.f;
        #pragma unroll
        for (int ni = 0; ni < NI; ni++) {
            int cl = warp_n * WN + ni * 8 + 2 * tig;
            float w0 = wa_s[cl], w1 = wa_s[cl + 1];
            float t;
            asm("tanh.approx.f32 %0, %1;" : "=f"(t) : "f"(acc[mi][ni][0] + hp0[cl]));     s0 += t * w0;
            asm("tanh.approx.f32 %0, %1;" : "=f"(t) : "f"(acc[mi][ni][1] + hp0[cl + 1])); s0 += t * w1;
            asm("tanh.approx.f32 %0, %1;" : "=f"(t) : "f"(acc[mi][ni][2] + hp1[cl]));     s1 += t * w0;
            asm("tanh.approx.f32 %0, %1;" : "=f"(t) : "f"(acc[mi][ni][3] + hp1[cl + 1])); s1 += t * w1;
        }
        s0 += __shfl_xor_sync(0xffffffffu, s0, 1);
        s0 += __shfl_xor_sync(0xffffffffu, s0, 2);
        s1 += __shfl_xor_sync(0xffffffffu, s1, 1);
        s1 += __shfl_xor_sync(0xffffffffu, s1, 2);
        if (tig == 0) {
            atomicAdd(&score[m0 + r0], s0);
            atomicAdd(&score[m0 + r1], s1);
        }
    }
}

// ================= small kernels =================
__global__ void zero_kernel(float* __restrict__ p, int n) {
    int i = blockIdx.x * blockDim.x + threadIdx.x;
    if (i < n) p[i] = 0.0f;
}

__global__ __launch_bounds__(256) void hproj_kernel(
    const float* __restrict__ hidden, const float* __restrict__ Wh,
    const float* __restrict__ bh, const float* __restrict__ bv,
    float* __restrict__ out)
{
    int b = blockIdx.x;
    int achunk = blockIdx.y;
    __shared__ float h[HIDDEN];
    for (int i = threadIdx.x; i < HIDDEN; i += 256)
        h[i] = hidden[b * HIDDEN + i];
    __syncthreads();
    int warp = threadIdx.x >> 5, lane = threadIdx.x & 31;
    for (int al = warp; al < 128; al += 8) {
        int a = achunk * 128 + al;
        const float* w = Wh + (size_t)a * HIDDEN;
        float acc = 0.f;
        #pragma unroll 8
        for (int k = lane; k < HIDDEN; k += 32) acc += w[k] * h[k];
        #pragma unroll
        for (int off = 16; off > 0; off >>= 1)
            acc += __shfl_xor_sync(0xffffffffu, acc, off);
        if (lane == 0) out[b * 1024 + a] = acc + bh[a] + bv[a];
    }
}

__global__ __launch_bounds__(256) void spatial_kernel(
    const float* __restrict__ obj, const float* __restrict__ frame,
    const float* __restrict__ score, float* __restrict__ feat)
{
    int bf = blockIdx.x;
    __shared__ float alpha[NN];
    if (threadIdx.x == 0) {
        float s[NN];
        float mx = -1e30f;
        #pragma unroll
        for (int n = 0; n < NN; n++) { s[n] = score[bf * NN + n]; mx = fmaxf(mx, s[n]); }
        float sum = 0.f;
        #pragma unroll
        for (int n = 0; n < NN; n++) { float e = expf(s[n] - mx); alpha[n] = e; sum += e; }
        float inv = 1.f / sum;
        #pragma unroll
        for (int n = 0; n < NN; n++) alpha[n] *= inv;
    }
    __syncthreads();

    const float* base = obj + (size_t)bf * NN * REGION;
    float* frow = feat + (size_t)bf * FEAT2;
    for (int d = threadIdx.x; d < REGION; d += 256) {
        float acc = 0.f;
        #pragma unroll 6
        for (int n = 0; n < NN; n++) acc += alpha[n] * base[(size_t)n * REGION + d];
        frow[d] = acc;
    }
    const float* frm = frame + (size_t)bf * (2 * HIDDEN);
    for (int d = threadIdx.x; d < 2 * HIDDEN; d += 256)
        frow[REGION + d] = frm[d];
}

__global__ __launch_bounds__(256) void temporal_kernel(
    const float* __restrict__ feat, const float* __restrict__ score2,
    float* __restrict__ out)
{
    int b = blockIdx.x;
    __shared__ float beta[FF];
    if (threadIdx.x == 0) {
        float s[FF];
        float mx = -1e30f;
        #pragma unroll
        for (int f = 0; f < FF; f++) { s[f] = score2[b * FF + f]; mx = fmaxf(mx, s[f]); }
        float sum = 0.f;
        #pragma unroll
        for (int f = 0; f < FF; f++) { float e = expf(s[f] - mx); beta[f] = e; sum += e; }
        float inv = 1.f / sum;
        #pragma unroll
        for (int f = 0; f < FF; f++) beta[f] *= inv;
    }
    __syncthreads();

    int d0 = blockIdx.y * (FEAT2 / 4);
    for (int d = d0 + threadIdx.x; d < d0 + FEAT2 / 4; d += 256) {
        float acc = 0.f;
        #pragma unroll 8
        for (int f = 0; f < FF; f++)
            acc += beta[f] * feat[((size_t)b * FF + f) * FEAT2 + d];
        out[(size_t)b * FEAT2 + d] = acc;
    }
}

// ================= launch =================
extern "C" void kernel_launch(void* const* d_in, const int* in_sizes, int n_in,
                              void* d_out, int out_size)
{
    const float* frame  = (const float*)d_in[0];
    const float* obj    = (const float*)d_in[1];
    const float* hidden = (const float*)d_in[2];
    const float* s_wh_w = (const float*)d_in[3];
    const float* s_wh_b = (const float*)d_in[4];
    const float* s_wv_w = (const float*)d_in[5];
    const float* s_wv_b = (const float*)d_in[6];
    const float* s_wa_w = (const float*)d_in[7];
    const float* t_wh_w = (const float*)d_in[8];
    const float* t_wh_b = (const float*)d_in[9];
    const float* t_wv_w = (const float*)d_in[10];
    const float* t_wv_b = (const float*)d_in[11];
    const float* t_wa_w = (const float*)d_in[12];
    float* out = (float*)d_out;

    float *p_hs, *p_ht, *p_s1, *p_feat, *p_s2;
    cudaGetSymbolAddress((void**)&p_hs, g_hproj_s);
    cudaGetSymbolAddress((void**)&p_ht, g_hproj_t);
    cudaGetSymbolAddress((void**)&p_s1, g_score1);
    cudaGetSymbolAddress((void**)&p_feat, g_feat);
    cudaGetSymbolAddress((void**)&p_s2, g_score2);

    // smem: 3*(16384 + NT*128) + NT*4 + 4*NT*4
    const int SMEM_256 = 3 * (16384 + 256 * 128) + 256 * 4 + 4 * 256 * 4;   // 152576
    const int SMEM_128 = 3 * (16384 + 128 * 128) + 128 * 4 + 4 * 128 * 4;   // 100864
    cudaFuncSetAttribute(gemm_score_mma<256>, cudaFuncAttributeMaxDynamicSharedMemorySize, SMEM_256);
    cudaFuncSetAttribute(gemm_score_mma<128>, cudaFuncAttributeMaxDynamicSharedMemorySize, SMEM_128);

    // hidden-state projections (fold in both biases)
    dim3 hg(BB, 8);
    hproj_kernel<<<hg, 256>>>(hidden, s_wh_w, s_wh_b, s_wv_b, p_hs);
    hproj_kernel<<<hg, 256>>>(hidden, t_wh_w, t_wh_b, t_wv_b, p_ht);

    // spatial attention scores: 155 GFLOP tf32 mma.sync GEMM, fused epilogue
    zero_kernel<<<(M1 + 255) / 256, 256>>>(p_s1, M1);
    gemm_score_mma<256><<<dim3(M1 / 128, 4), 256, SMEM_256>>>(
        obj, s_wv_w, p_hs, s_wa_w, p_s1, REGION, FF * NN);

    // softmax over boxes + weighted object sum + concat frame feats
    spatial_kernel<<<M2, 256>>>(obj, frame, p_s1, p_feat);

    // temporal attention scores (NT=128 -> 16x8 = 128 CTAs)
    zero_kernel<<<(M2 + 255) / 256, 256>>>(p_s2, M2);
    gemm_score_mma<128><<<dim3(M2 / 128, 8), 256, SMEM_128>>>(
        p_feat, t_wv_w, p_ht, t_wa_w, p_s2, FEAT2, FF);

    // softmax over frames + weighted feat sum -> [64, 3072]
    temporal_kernel<<<dim3(BB, 4), 256>>>(p_feat, p_s2, out);
}